// round 10
// baseline (speedup 1.0000x reference)
#include <cuda_runtime.h>
#include <cuda_fp16.h>
#include <cstdint>

#define NN 100000
#define EE 3200000
#define HID 32
#define DIN 128
#define SCAN_B 256
#define AGG_T 512
#define MAXB ((NN * 8 + AGG_T - 1) / AGG_T + 1)

// ---------------- scratch ----------------
__device__ __align__(16) __half g_tmph[NN * HID]; // h@W fp16 (64B/row)
__device__ __align__(16) float g_acc[NN * HID];   // conv result (fp32)
__device__ float g_deg[NN];
__device__ float g_selfnorm[NN];
__device__ int   g_cnt[NN];
__device__ int   g_off[NN + 1];
__device__ __align__(16) int2 g_edge[EE + 8];     // +tail for clamped reads
__device__ int   g_bsum[512];
__device__ int   g_boff[512];
__device__ float g_part[MAXB * 64];
__device__ float g_stats[64];

// ---------------- prep ----------------
__global__ void k_init(int n) {
    int i = blockIdx.x * blockDim.x + threadIdx.x;
    if (i < n) { g_deg[i] = 1.0f; g_cnt[i] = 0; }
}

__global__ void k_degree_hist(const int* __restrict__ ei,
                              const float* __restrict__ w, int e_cnt, int n) {
    int e = blockIdx.x * blockDim.x + threadIdx.x;
    if (e < e_cnt) {
        int c = ei[e_cnt + e];
        c = min(max(c, 0), n - 1);
        atomicAdd(&g_deg[c], w[e]);
        atomicAdd(&g_cnt[c], 1);
    }
}

__global__ void k_dinv(int n) {
    int i = blockIdx.x * blockDim.x + threadIdx.x;
    if (i < n) {
        float d = g_deg[i];
        float di = (d > 0.f) ? rsqrtf(d) : 0.f;
        g_deg[i] = di;
        g_selfnorm[i] = di * di;
    }
}

__global__ void k_scan_a(int n) {
    __shared__ int sh[SCAN_B];
    int i = blockIdx.x * SCAN_B + threadIdx.x;
    sh[threadIdx.x] = (i < n) ? g_cnt[i] : 0;
    __syncthreads();
    for (int off = SCAN_B / 2; off > 0; off >>= 1) {
        if (threadIdx.x < off) sh[threadIdx.x] += sh[threadIdx.x + off];
        __syncthreads();
    }
    if (threadIdx.x == 0) g_bsum[blockIdx.x] = sh[0];
}

__global__ void k_scan_b(int nb) {
    __shared__ int sh[512];
    int tid = threadIdx.x;
    sh[tid] = (tid < nb) ? g_bsum[tid] : 0;
    __syncthreads();
    for (int off = 1; off < 512; off <<= 1) {
        int v = (tid >= off) ? sh[tid - off] : 0;
        __syncthreads();
        sh[tid] += v;
        __syncthreads();
    }
    if (tid < nb) g_boff[tid] = sh[tid] - g_bsum[tid];
}

__global__ void k_scan_c(int n, int e_cnt) {
    __shared__ int sh[SCAN_B];
    int tid = threadIdx.x;
    int i = blockIdx.x * SCAN_B + tid;
    int c = (i < n) ? g_cnt[i] : 0;
    sh[tid] = c;
    __syncthreads();
    for (int off = 1; off < SCAN_B; off <<= 1) {
        int v = (tid >= off) ? sh[tid - off] : 0;
        __syncthreads();
        sh[tid] += v;
        __syncthreads();
    }
    if (i < n) {
        int off = g_boff[blockIdx.x] + sh[tid] - c;
        g_off[i] = off;
        g_cnt[i] = off;
    }
    if (blockIdx.x == 0 && tid == 0) g_off[n] = e_cnt;
}

__global__ void k_csr_scatter(const int* __restrict__ ei,
                              const float* __restrict__ w, int e_cnt, int n) {
    int e = blockIdx.x * blockDim.x + threadIdx.x;
    if (e < e_cnt) {
        int r = ei[e];
        int c = ei[e_cnt + e];
        r = min(max(r, 0), n - 1);
        c = min(max(c, 0), n - 1);
        int pos = atomicAdd(&g_cnt[c], 1);
        float nm = g_deg[r] * w[e] * g_deg[c];
        g_edge[pos] = make_int2(r, __float_as_int(nm));
    }
}

// ---------------- transforms (write fp16 gather table) ----------------
__global__ void k_gemm128(const float* __restrict__ x,
                          const float* __restrict__ W, int n) {
    __shared__ float Ws[DIN * HID];
    __shared__ float xs[8][DIN];
    int tid = threadIdx.x;
    for (int i = tid; i < DIN * HID; i += 256) Ws[i] = W[i];
    __syncthreads();
    int warp = tid >> 5, lane = tid & 31;
    int r = blockIdx.x * 8 + warp;
    if (r >= n) return;
#pragma unroll
    for (int j = 0; j < 4; j++)
        xs[warp][j * 32 + lane] = x[r * DIN + j * 32 + lane];
    __syncwarp();
    float sum = 0.f;
#pragma unroll
    for (int k = 0; k < DIN; k++) sum += xs[warp][k] * Ws[k * HID + lane];
    g_tmph[r * HID + lane] = __float2half(sum);
}

__global__ void k_gemm32_bn(const float* __restrict__ W,
                            const float* __restrict__ g,
                            const float* __restrict__ be, int n, float invN) {
    __shared__ float Ws[HID * HID];
    __shared__ float bn_s[HID], bn_b[HID];
    int tid = threadIdx.x;
    for (int i = tid; i < HID * HID; i += 256) Ws[i] = W[i];
    if (tid < HID) {
        float mu  = g_stats[tid] * invN;
        float var = g_stats[32 + tid] * invN - mu * mu;
        float sc  = rsqrtf(var + 1e-5f) * g[tid];
        bn_s[tid] = sc;
        bn_b[tid] = be[tid] - mu * sc;
    }
    __syncthreads();
    int warp = tid >> 5, lane = tid & 31;
    int r = blockIdx.x * 8 + warp;
    if (r >= n) return;
    float mine = fmaxf(g_acc[r * HID + lane] * bn_s[lane] + bn_b[lane], 0.f);
    float sum = 0.f;
#pragma unroll
    for (int k = 0; k < HID; k++) {
        float xv = __shfl_sync(0xffffffffu, mine, k);
        sum += xv * Ws[k * HID + lane];
    }
    g_tmph[r * HID + lane] = __float2half(sum);
}

// ---------------- CSR gather-aggregate: 4 nodes/warp, 8 lanes/node ------
// lane = 8*sub + col4; node v = warp_id*4 + sub; lane covers cols 4*col4..+3
// Edge loop runs to warp-max degree with mask predication so all lanes stay
// converged -> each LDG warp-instruction serves 4 edges.
__global__ void __launch_bounds__(AGG_T)
k_aggregate(const float* __restrict__ b, int n, int do_stats,
            float* __restrict__ out) {
    const uint2* __restrict__ tmp16 = (const uint2*)g_tmph;  // 8 uint2/row
    int t = blockIdx.x * AGG_T + threadIdx.x;
    int wglob = t >> 5;
    int sub   = (t >> 3) & 3;
    int col4  = t & 7;
    int v = wglob * 4 + sub;
    bool valid = (v < n);
    int vc = valid ? v : 0;

    int beg = g_off[vc];
    int deg = g_off[vc + 1] - beg;
    if (!valid) deg = 0;
    // warp-uniform max degree over the 4 sub-groups
    int m = max(deg, __shfl_xor_sync(0xffffffffu, deg, 8));
    int maxdeg = max(m, __shfl_xor_sync(0xffffffffu, m, 16));

    // init: bias + self-loop
    float4 acc;
    {
        uint2 u = tmp16[vc * 8 + col4];
        float2 f01 = __half22float2(*(__half2*)&u.x);
        float2 f23 = __half22float2(*(__half2*)&u.y);
        float sn = g_selfnorm[vc];
        const float4* b4 = (const float4*)b;
        float4 bb = b4[col4 >> 1];   // b is 32 floats = 8 float4... careful
        // cols for this lane: c0 = col4*4 .. need b[c0..c0+3] = b4[col4]
        bb = ((const float4*)b)[col4];
        acc.x = bb.x + sn * f01.x;
        acc.y = bb.y + sn * f01.y;
        acc.z = bb.z + sn * f23.x;
        acc.w = bb.w + sn * f23.y;
    }

    int dm1 = max(deg - 1, 0);
    for (int i = 0; i < maxdeg; i += 4) {
#pragma unroll
        for (int k = 0; k < 4; k++) {
            int idx = beg + min(i + k, dm1);
            int2 e = g_edge[idx];
            float msk = (i + k < deg) ? 1.f : 0.f;
            float nm = __int_as_float(e.y) * msk;
            int r = min(max(e.x, 0), n - 1);
            uint2 u = tmp16[r * 8 + col4];
            float2 f01 = __half22float2(*(__half2*)&u.x);
            float2 f23 = __half22float2(*(__half2*)&u.y);
            acc.x += nm * f01.x;
            acc.y += nm * f01.y;
            acc.z += nm * f23.x;
            acc.w += nm * f23.y;
        }
    }

    if (valid) {
        if (out) {
            float4 o;
            o.x = fmaxf(acc.x, 0.f);
            o.y = fmaxf(acc.y, 0.f);
            o.z = fmaxf(acc.z, 0.f);
            o.w = fmaxf(acc.w, 0.f);
            ((float4*)out)[v * 8 + col4] = o;
        } else {
            ((float4*)g_acc)[v * 8 + col4] = acc;
        }
    }

    if (do_stats) {
        int warp = threadIdx.x >> 5;
        int lane = threadIdx.x & 31;
        float4 s = valid ? acc : make_float4(0, 0, 0, 0);
        float4 q;
        q.x = s.x * s.x; q.y = s.y * s.y; q.z = s.z * s.z; q.w = s.w * s.w;
        // reduce over the 4 sub-groups (lane bits 3,4)
#pragma unroll
        for (int off = 8; off <= 16; off <<= 1) {
            s.x += __shfl_xor_sync(0xffffffffu, s.x, off);
            s.y += __shfl_xor_sync(0xffffffffu, s.y, off);
            s.z += __shfl_xor_sync(0xffffffffu, s.z, off);
            s.w += __shfl_xor_sync(0xffffffffu, s.w, off);
            q.x += __shfl_xor_sync(0xffffffffu, q.x, off);
            q.y += __shfl_xor_sync(0xffffffffu, q.y, off);
            q.z += __shfl_xor_sync(0xffffffffu, q.z, off);
            q.w += __shfl_xor_sync(0xffffffffu, q.w, off);
        }
        __shared__ float sh[AGG_T / 32][64];
        if (lane < 8) {
            int c0 = lane * 4;
            sh[warp][c0 + 0] = s.x;
            sh[warp][c0 + 1] = s.y;
            sh[warp][c0 + 2] = s.z;
            sh[warp][c0 + 3] = s.w;
            sh[warp][32 + c0 + 0] = q.x;
            sh[warp][32 + c0 + 1] = q.y;
            sh[warp][32 + c0 + 2] = q.z;
            sh[warp][32 + c0 + 3] = q.w;
        }
        __syncthreads();
        if (threadIdx.x < 64) {
            float tt = 0.f;
#pragma unroll
            for (int w2 = 0; w2 < AGG_T / 32; w2++) tt += sh[w2][threadIdx.x];
            g_part[blockIdx.x * 64 + threadIdx.x] = tt;
        }
    }
}

__global__ void k_redstats(int nb) {
    __shared__ float sh[256];
    int j = blockIdx.x;
    int tid = threadIdx.x;
    float s = 0.f;
    for (int b2 = tid; b2 < nb; b2 += 256) s += g_part[b2 * 64 + j];
    sh[tid] = s;
    __syncthreads();
    for (int off = 128; off > 0; off >>= 1) {
        if (tid < off) sh[tid] += sh[tid + off];
        __syncthreads();
    }
    if (tid == 0) g_stats[j] = sh[0];
}

// ---------------- launch ----------------
extern "C" void kernel_launch(void* const* d_in, const int* in_sizes, int n_in,
                              void* d_out, int out_size) {
    const float* x  = (const float*)d_in[0];
    const int*   ei = (const int*)d_in[1];
    const float* w  = (const float*)d_in[2];
    const float* W0 = (const float*)d_in[3];
    const float* b0 = (const float*)d_in[4];
    const float* W1 = (const float*)d_in[5];
    const float* b1 = (const float*)d_in[6];
    const float* W2 = (const float*)d_in[7];
    const float* b2 = (const float*)d_in[8];
    const float* W3 = (const float*)d_in[9];
    const float* b3 = (const float*)d_in[10];
    const float* g0 = (const float*)d_in[11];
    const float* be0 = (const float*)d_in[12];
    const float* g1 = (const float*)d_in[13];
    const float* be1 = (const float*)d_in[14];
    const float* g2 = (const float*)d_in[15];
    const float* be2 = (const float*)d_in[16];
    float* out = (float*)d_out;

    const int n = in_sizes[0] / DIN;        // 100000
    const int e = in_sizes[2];              // 3200000
    const float invN = 1.0f / (float)n;

    const int TB = 256;
    const int gN   = (n + TB - 1) / TB;
    const int gE   = (e + TB - 1) / TB;
    const int gAgg = (n * 8 + AGG_T - 1) / AGG_T;   // 8 threads per node
    const int gRow = (n + 7) / 8;
    const int nb   = (n + SCAN_B - 1) / SCAN_B;

    k_init<<<gN, TB>>>(n);
    k_degree_hist<<<gE, TB>>>(ei, w, e, n);
    k_dinv<<<gN, TB>>>(n);
    k_scan_a<<<nb, SCAN_B>>>(n);
    k_scan_b<<<1, 512>>>(nb);
    k_scan_c<<<nb, SCAN_B>>>(n, e);
    k_csr_scatter<<<gE, TB>>>(ei, w, e, n);

    const float* Ws[4]  = {W0, W1, W2, W3};
    const float* bs[4]  = {b0, b1, b2, b3};
    const float* gs[3]  = {g0, g1, g2};
    const float* bes[3] = {be0, be1, be2};

    for (int layer = 0; layer < 4; layer++) {
        if (layer == 0)
            k_gemm128<<<gRow, TB>>>(x, Ws[0], n);
        else
            k_gemm32_bn<<<gRow, TB>>>(Ws[layer], gs[layer - 1],
                                      bes[layer - 1], n, invN);
        if (layer < 3) {
            k_aggregate<<<gAgg, AGG_T>>>(bs[layer], n, 1, nullptr);
            k_redstats<<<64, 256>>>(gAgg);
        } else {
            k_aggregate<<<gAgg, AGG_T>>>(bs[layer], n, 0, out);
        }
    }
}

// round 11
// speedup vs baseline: 1.4126x; 1.4126x over previous
#include <cuda_runtime.h>
#include <cuda_fp16.h>
#include <cstdint>

#define NN 100000
#define EE 3200000
#define HID 32
#define DIN 128
#define SCAN_B 256
#define AGG_T 512
#define NBLK ((NN * 32 + AGG_T - 1) / AGG_T)   // 6250 aggregate blocks
#define PSTR 6272                               // padded stride for g_part

// ---------------- scratch ----------------
__device__ float g_tmp[NN * HID];   // h @ W (gather source, fp32)
__device__ float g_acc[NN * HID];   // conv result
__device__ unsigned long long g_hist[NN];  // packed {count:12 | weight_fx:52}
__device__ float g_deg[NN];         // dinv
__device__ float g_selfnorm[NN];    // dinv^2
__device__ int   g_cnt[NN];         // counts, then CSR cursor
__device__ int   g_off[NN + 1];     // CSR offsets
__device__ int2  g_edge[EE];        // CSR: {src, float-bits of norm}
__device__ int   g_bsum[512];
__device__ int   g_boff[512];
__device__ float g_part[64 * PSTR]; // transposed partial BN stats
__device__ float g_stats[64];

// ---------------- prep ----------------
__global__ void k_init(int n) {
    int i = blockIdx.x * blockDim.x + threadIdx.x;
    if (i < n) g_hist[i] = 0ULL;
}

// one packed atomic per edge: count += 1 (bit 52), weight += w * 2^32
__global__ void k_hist(const int* __restrict__ ei,
                       const float* __restrict__ w, int e_cnt, int n) {
    int e = blockIdx.x * blockDim.x + threadIdx.x;
    if (e < e_cnt) {
        int c = ei[e_cnt + e];
        c = min(max(c, 0), n - 1);
        unsigned long long wf =
            (unsigned long long)(fmaxf(w[e], 0.f) * 4294967296.0f + 0.5f);
        atomicAdd(&g_hist[c], (1ULL << 52) | wf);
    }
}

// scan_a fused with unpack + dinv + selfnorm
__global__ void k_scan_a(int n) {
    __shared__ int sh[SCAN_B];
    int i = blockIdx.x * SCAN_B + threadIdx.x;
    int cnt = 0;
    if (i < n) {
        unsigned long long h = g_hist[i];
        cnt = (int)(h >> 52);
        float wsum = (float)(h & ((1ULL << 52) - 1ULL)) * 2.3283064365386963e-10f
                     + 1.0f;   // + self-loop
        float di = rsqrtf(wsum);   // wsum >= 1 always
        g_deg[i] = di;
        g_selfnorm[i] = di * di;
        g_cnt[i] = cnt;
    }
    sh[threadIdx.x] = cnt;
    __syncthreads();
    for (int off = SCAN_B / 2; off > 0; off >>= 1) {
        if (threadIdx.x < off) sh[threadIdx.x] += sh[threadIdx.x + off];
        __syncthreads();
    }
    if (threadIdx.x == 0) g_bsum[blockIdx.x] = sh[0];
}

__global__ void k_scan_b(int nb) {
    __shared__ int sh[512];
    int tid = threadIdx.x;
    sh[tid] = (tid < nb) ? g_bsum[tid] : 0;
    __syncthreads();
    for (int off = 1; off < 512; off <<= 1) {
        int v = (tid >= off) ? sh[tid - off] : 0;
        __syncthreads();
        sh[tid] += v;
        __syncthreads();
    }
    if (tid < nb) g_boff[tid] = sh[tid] - g_bsum[tid];
}

__global__ void k_scan_c(int n, int e_cnt) {
    __shared__ int sh[SCAN_B];
    int tid = threadIdx.x;
    int i = blockIdx.x * SCAN_B + tid;
    int c = (i < n) ? g_cnt[i] : 0;
    sh[tid] = c;
    __syncthreads();
    for (int off = 1; off < SCAN_B; off <<= 1) {
        int v = (tid >= off) ? sh[tid - off] : 0;
        __syncthreads();
        sh[tid] += v;
        __syncthreads();
    }
    if (i < n) {
        int off = g_boff[blockIdx.x] + sh[tid] - c;
        g_off[i] = off;
        g_cnt[i] = off;
    }
    if (blockIdx.x == 0 && tid == 0) g_off[n] = e_cnt;
}

__global__ void k_csr_scatter(const int* __restrict__ ei,
                              const float* __restrict__ w, int e_cnt, int n) {
    int e = blockIdx.x * blockDim.x + threadIdx.x;
    if (e < e_cnt) {
        int r = ei[e];
        int c = ei[e_cnt + e];
        r = min(max(r, 0), n - 1);
        c = min(max(c, 0), n - 1);
        int pos = atomicAdd(&g_cnt[c], 1);
        float nm = g_deg[r] * w[e] * g_deg[c];
        g_edge[pos] = make_int2(r, __float_as_int(nm));
    }
}

// ---------------- transforms ----------------
__global__ void k_gemm128(const float* __restrict__ x,
                          const float* __restrict__ W, int n) {
    __shared__ float Ws[DIN * HID];
    __shared__ float xs[8][DIN];
    int tid = threadIdx.x;
    for (int i = tid; i < DIN * HID; i += 256) Ws[i] = W[i];
    __syncthreads();
    int warp = tid >> 5, lane = tid & 31;
    int r = blockIdx.x * 8 + warp;
    if (r >= n) return;
#pragma unroll
    for (int j = 0; j < 4; j++)
        xs[warp][j * 32 + lane] = x[r * DIN + j * 32 + lane];
    __syncwarp();
    float sum = 0.f;
#pragma unroll
    for (int k = 0; k < DIN; k++) sum += xs[warp][k] * Ws[k * HID + lane];
    g_tmp[r * HID + lane] = sum;
}

__global__ void k_gemm32_bn(const float* __restrict__ W,
                            const float* __restrict__ g,
                            const float* __restrict__ be, int n, float invN) {
    __shared__ float Ws[HID * HID];
    __shared__ float bn_s[HID], bn_b[HID];
    int tid = threadIdx.x;
    for (int i = tid; i < HID * HID; i += 256) Ws[i] = W[i];
    if (tid < HID) {
        float mu  = g_stats[tid] * invN;
        float var = g_stats[32 + tid] * invN - mu * mu;
        float sc  = rsqrtf(var + 1e-5f) * g[tid];
        bn_s[tid] = sc;
        bn_b[tid] = be[tid] - mu * sc;
    }
    __syncthreads();
    int warp = tid >> 5, lane = tid & 31;
    int r = blockIdx.x * 8 + warp;
    if (r >= n) return;
    float mine = fmaxf(g_acc[r * HID + lane] * bn_s[lane] + bn_b[lane], 0.f);
    float sum = 0.f;
#pragma unroll
    for (int k = 0; k < HID; k++) {
        float xv = __shfl_sync(0xffffffffu, mine, k);
        sum += xv * Ws[k * HID + lane];
    }
    g_tmp[r * HID + lane] = sum;
}

// ---------------- CSR gather-aggregate (R8 champion core) ---------------
__global__ void __launch_bounds__(AGG_T)
k_aggregate(const float* __restrict__ b, int n, int do_stats,
            float* __restrict__ out) {
    int gid = blockIdx.x * AGG_T + threadIdx.x;
    int v = gid >> 5;
    int lane = gid & 31;
    int warp = threadIdx.x >> 5;
    float acc = 0.f;
    if (v < n) {
        int beg = g_off[v];
        int end = g_off[v + 1];
        acc = b[lane] + g_selfnorm[v] * g_tmp[v * HID + lane];
        int i = beg;
        for (; i + 8 <= end; i += 8) {
            int2 e0 = g_edge[i + 0];
            int2 e1 = g_edge[i + 1];
            int2 e2 = g_edge[i + 2];
            int2 e3 = g_edge[i + 3];
            int2 e4 = g_edge[i + 4];
            int2 e5 = g_edge[i + 5];
            int2 e6 = g_edge[i + 6];
            int2 e7 = g_edge[i + 7];
            float f0 = g_tmp[e0.x * HID + lane];
            float f1 = g_tmp[e1.x * HID + lane];
            float f2 = g_tmp[e2.x * HID + lane];
            float f3 = g_tmp[e3.x * HID + lane];
            float f4 = g_tmp[e4.x * HID + lane];
            float f5 = g_tmp[e5.x * HID + lane];
            float f6 = g_tmp[e6.x * HID + lane];
            float f7 = g_tmp[e7.x * HID + lane];
            acc += __int_as_float(e0.y) * f0;
            acc += __int_as_float(e1.y) * f1;
            acc += __int_as_float(e2.y) * f2;
            acc += __int_as_float(e3.y) * f3;
            acc += __int_as_float(e4.y) * f4;
            acc += __int_as_float(e5.y) * f5;
            acc += __int_as_float(e6.y) * f6;
            acc += __int_as_float(e7.y) * f7;
        }
        if (i + 4 <= end) {
            int2 e0 = g_edge[i + 0];
            int2 e1 = g_edge[i + 1];
            int2 e2 = g_edge[i + 2];
            int2 e3 = g_edge[i + 3];
            float f0 = g_tmp[e0.x * HID + lane];
            float f1 = g_tmp[e1.x * HID + lane];
            float f2 = g_tmp[e2.x * HID + lane];
            float f3 = g_tmp[e3.x * HID + lane];
            acc += __int_as_float(e0.y) * f0;
            acc += __int_as_float(e1.y) * f1;
            acc += __int_as_float(e2.y) * f2;
            acc += __int_as_float(e3.y) * f3;
            i += 4;
        }
        for (; i < end; i++) {
            int2 e0 = g_edge[i];
            acc += __int_as_float(e0.y) * g_tmp[e0.x * HID + lane];
        }
        if (out) out[v * HID + lane] = fmaxf(acc, 0.f);
        else     g_acc[v * HID + lane] = acc;
    }
    if (do_stats) {
        __shared__ float sh[16][64];
        float a = (v < n) ? acc : 0.f;
        sh[warp][lane]      = a;
        sh[warp][32 + lane] = a * a;
        __syncthreads();
        if (threadIdx.x < 64) {
            float t = 0.f;
#pragma unroll
            for (int w = 0; w < 16; w++) t += sh[w][threadIdx.x];
            g_part[threadIdx.x * PSTR + blockIdx.x] = t;   // transposed
        }
    }
}

// block j reduces row j of g_part (coalesced reads)
__global__ void k_redstats(int nb) {
    __shared__ float sh[256];
    int j = blockIdx.x;
    int tid = threadIdx.x;
    float s = 0.f;
    for (int b2 = tid; b2 < nb; b2 += 256) s += g_part[j * PSTR + b2];
    sh[tid] = s;
    __syncthreads();
    for (int off = 128; off > 0; off >>= 1) {
        if (tid < off) sh[tid] += sh[tid + off];
        __syncthreads();
    }
    if (tid == 0) g_stats[j] = sh[0];
}

// ---------------- launch ----------------
extern "C" void kernel_launch(void* const* d_in, const int* in_sizes, int n_in,
                              void* d_out, int out_size) {
    const float* x  = (const float*)d_in[0];
    const int*   ei = (const int*)d_in[1];     // int32 (harness dtype)
    const float* w  = (const float*)d_in[2];
    const float* W0 = (const float*)d_in[3];
    const float* b0 = (const float*)d_in[4];
    const float* W1 = (const float*)d_in[5];
    const float* b1 = (const float*)d_in[6];
    const float* W2 = (const float*)d_in[7];
    const float* b2 = (const float*)d_in[8];
    const float* W3 = (const float*)d_in[9];
    const float* b3 = (const float*)d_in[10];
    const float* g0 = (const float*)d_in[11];
    const float* be0 = (const float*)d_in[12];
    const float* g1 = (const float*)d_in[13];
    const float* be1 = (const float*)d_in[14];
    const float* g2 = (const float*)d_in[15];
    const float* be2 = (const float*)d_in[16];
    float* out = (float*)d_out;

    const int n = in_sizes[0] / DIN;        // 100000
    const int e = in_sizes[2];              // 3200000
    const float invN = 1.0f / (float)n;

    const int TB = 256;
    const int gN   = (n + TB - 1) / TB;
    const int gE   = (e + TB - 1) / TB;
    const int gAgg = (n * 32 + AGG_T - 1) / AGG_T;  // 6250
    const int gRow = (n + 7) / 8;
    const int nb   = (n + SCAN_B - 1) / SCAN_B;

    // ---- CSR + normalization precompute ----
    k_init<<<gN, TB>>>(n);
    k_hist<<<gE, TB>>>(ei, w, e, n);
    k_scan_a<<<nb, SCAN_B>>>(n);        // unpack + dinv fused
    k_scan_b<<<1, 512>>>(nb);
    k_scan_c<<<nb, SCAN_B>>>(n, e);
    k_csr_scatter<<<gE, TB>>>(ei, w, e, n);

    const float* Ws[4]  = {W0, W1, W2, W3};
    const float* bs[4]  = {b0, b1, b2, b3};
    const float* gs[3]  = {g0, g1, g2};
    const float* bes[3] = {be0, be1, be2};

    for (int layer = 0; layer < 4; layer++) {
        if (layer == 0)
            k_gemm128<<<gRow, TB>>>(x, Ws[0], n);
        else
            k_gemm32_bn<<<gRow, TB>>>(Ws[layer], gs[layer - 1],
                                      bes[layer - 1], n, invN);
        if (layer < 3) {
            k_aggregate<<<gAgg, AGG_T>>>(bs[layer], n, 1, nullptr);
            k_redstats<<<64, 256>>>(gAgg);
        } else {
            k_aggregate<<<gAgg, AGG_T>>>(bs[layer], n, 0, out);
        }
    }
}

// round 12
// speedup vs baseline: 1.4243x; 1.0083x over previous
#include <cuda_runtime.h>
#include <cuda_fp16.h>
#include <cstdint>

#define NN 100000
#define EE 3200000
#define HID 32
#define DIN 128
#define SCAN_B 256
#define AGG_T 512
#define NREP 32                                 // stat replicas per layer

// ---------------- scratch ----------------
__device__ float g_tmp[NN * HID];   // h @ W (gather source, fp32)
__device__ float g_acc[NN * HID];   // conv result
__device__ unsigned long long g_hist[NN];  // packed {count:12 | weight_fx:52}
__device__ float g_deg[NN];         // dinv
__device__ float g_selfnorm[NN];    // dinv^2
__device__ int   g_cnt[NN];         // counts, then CSR cursor
__device__ int   g_off[NN + 1];     // CSR offsets
__device__ int2  g_edge[EE];        // CSR: {src, float-bits of norm}
__device__ int   g_bsum[512];       // scan block sums
__device__ float g_statsR[3 * NREP * 64];  // replicated BN partials

// ---------------- prep ----------------
__global__ void k_init(int n) {
    int i = blockIdx.x * blockDim.x + threadIdx.x;
    if (i < n) g_hist[i] = 0ULL;
    if (i < 3 * NREP * 64) g_statsR[i] = 0.f;
}

// one packed atomic per edge: count += 1 (bit 52), weight += w * 2^32
__global__ void k_hist(const int* __restrict__ ei,
                       const float* __restrict__ w, int e_cnt, int n) {
    int e = blockIdx.x * blockDim.x + threadIdx.x;
    if (e < e_cnt) {
        int c = ei[e_cnt + e];
        c = min(max(c, 0), n - 1);
        unsigned long long wf =
            (unsigned long long)(fmaxf(w[e], 0.f) * 4294967296.0f + 0.5f);
        atomicAdd(&g_hist[c], (1ULL << 52) | wf);
    }
}

// scan_a fused with unpack + dinv + selfnorm
__global__ void k_scan_a(int n) {
    __shared__ int sh[SCAN_B];
    int i = blockIdx.x * SCAN_B + threadIdx.x;
    int cnt = 0;
    if (i < n) {
        unsigned long long h = g_hist[i];
        cnt = (int)(h >> 52);
        float wsum = (float)(h & ((1ULL << 52) - 1ULL)) * 2.3283064365386963e-10f
                     + 1.0f;   // + self-loop
        float di = rsqrtf(wsum);
        g_deg[i] = di;
        g_selfnorm[i] = di * di;
        g_cnt[i] = cnt;
    }
    sh[threadIdx.x] = cnt;
    __syncthreads();
    for (int off = SCAN_B / 2; off > 0; off >>= 1) {
        if (threadIdx.x < off) sh[threadIdx.x] += sh[threadIdx.x + off];
        __syncthreads();
    }
    if (threadIdx.x == 0) g_bsum[blockIdx.x] = sh[0];
}

// scan_c computes its own global offset from g_bsum (scan_b eliminated)
__global__ void k_scan_c(int n, int e_cnt) {
    __shared__ int sh[SCAN_B];
    __shared__ int base_s;
    int tid = threadIdx.x;
    // sum of g_bsum[j] for j < blockIdx.x
    int s = 0;
    for (int j = tid; j < blockIdx.x; j += SCAN_B) s += g_bsum[j];
    sh[tid] = s;
    __syncthreads();
    for (int off = SCAN_B / 2; off > 0; off >>= 1) {
        if (tid < off) sh[tid] += sh[tid + off];
        __syncthreads();
    }
    if (tid == 0) base_s = sh[0];
    __syncthreads();
    int base = base_s;
    __syncthreads();   // sh reused below

    int i = blockIdx.x * SCAN_B + tid;
    int c = (i < n) ? g_cnt[i] : 0;
    sh[tid] = c;
    __syncthreads();
    for (int off = 1; off < SCAN_B; off <<= 1) {
        int v = (tid >= off) ? sh[tid - off] : 0;
        __syncthreads();
        sh[tid] += v;
        __syncthreads();
    }
    if (i < n) {
        int off = base + sh[tid] - c;   // exclusive
        g_off[i] = off;
        g_cnt[i] = off;                 // cursor
    }
    if (blockIdx.x == 0 && tid == 0) g_off[n] = e_cnt;
}

__global__ void k_csr_scatter(const int* __restrict__ ei,
                              const float* __restrict__ w, int e_cnt, int n) {
    int e = blockIdx.x * blockDim.x + threadIdx.x;
    if (e < e_cnt) {
        int r = ei[e];
        int c = ei[e_cnt + e];
        r = min(max(r, 0), n - 1);
        c = min(max(c, 0), n - 1);
        int pos = atomicAdd(&g_cnt[c], 1);
        float nm = g_deg[r] * w[e] * g_deg[c];
        g_edge[pos] = make_int2(r, __float_as_int(nm));
    }
}

// ---------------- transforms ----------------
__global__ void k_gemm128(const float* __restrict__ x,
                          const float* __restrict__ W, int n) {
    __shared__ float Ws[DIN * HID];
    __shared__ float xs[8][DIN];
    int tid = threadIdx.x;
    for (int i = tid; i < DIN * HID; i += 256) Ws[i] = W[i];
    __syncthreads();
    int warp = tid >> 5, lane = tid & 31;
    int r = blockIdx.x * 8 + warp;
    if (r >= n) return;
#pragma unroll
    for (int j = 0; j < 4; j++)
        xs[warp][j * 32 + lane] = x[r * DIN + j * 32 + lane];
    __syncwarp();
    float sum = 0.f;
#pragma unroll
    for (int k = 0; k < DIN; k++) sum += xs[warp][k] * Ws[k * HID + lane];
    g_tmp[r * HID + lane] = sum;
}

// prologue reduces the NREP stat replicas of the previous layer
__global__ void k_gemm32_bn(const float* __restrict__ W,
                            const float* __restrict__ g,
                            const float* __restrict__ be,
                            int n, float invN, int layerm1) {
    __shared__ float Ws[HID * HID];
    __shared__ float bn_s[HID], bn_b[HID];
    int tid = threadIdx.x;
    for (int i = tid; i < HID * HID; i += 256) Ws[i] = W[i];
    if (tid < 64) {
        const float* base = &g_statsR[layerm1 * NREP * 64];
        float s = 0.f;
#pragma unroll
        for (int r2 = 0; r2 < NREP; r2++) s += base[r2 * 64 + tid];
        if (tid < 32) {
            // s = sum over column tid; need sumsq too -> handled below
            bn_s[tid] = s;          // temporarily stash sum
        } else {
            bn_b[tid - 32] = s;     // temporarily stash sumsq
        }
    }
    __syncthreads();
    if (tid < HID) {
        float mu  = bn_s[tid] * invN;
        float var = bn_b[tid] * invN - mu * mu;
        float sc  = rsqrtf(var + 1e-5f) * g[tid];
        bn_s[tid] = sc;
        bn_b[tid] = be[tid] - mu * sc;
    }
    __syncthreads();
    int warp = tid >> 5, lane = tid & 31;
    int r = blockIdx.x * 8 + warp;
    if (r >= n) return;
    float mine = fmaxf(g_acc[r * HID + lane] * bn_s[lane] + bn_b[lane], 0.f);
    float sum = 0.f;
#pragma unroll
    for (int k = 0; k < HID; k++) {
        float xv = __shfl_sync(0xffffffffu, mine, k);
        sum += xv * Ws[k * HID + lane];
    }
    g_tmp[r * HID + lane] = sum;
}

// ---------------- CSR gather-aggregate ----------------
__global__ void __launch_bounds__(AGG_T)
k_aggregate(const float* __restrict__ b, int n, int layer,
            float* __restrict__ out) {
    int gid = blockIdx.x * AGG_T + threadIdx.x;
    int v = gid >> 5;
    int lane = gid & 31;
    int warp = threadIdx.x >> 5;
    float acc = 0.f;
    if (v < n) {
        int beg = g_off[v];
        int end = g_off[v + 1];
        acc = b[lane] + g_selfnorm[v] * g_tmp[v * HID + lane];
        int i = beg;
        for (; i + 8 <= end; i += 8) {
            int2 e0 = g_edge[i + 0];
            int2 e1 = g_edge[i + 1];
            int2 e2 = g_edge[i + 2];
            int2 e3 = g_edge[i + 3];
            int2 e4 = g_edge[i + 4];
            int2 e5 = g_edge[i + 5];
            int2 e6 = g_edge[i + 6];
            int2 e7 = g_edge[i + 7];
            float f0 = g_tmp[e0.x * HID + lane];
            float f1 = g_tmp[e1.x * HID + lane];
            float f2 = g_tmp[e2.x * HID + lane];
            float f3 = g_tmp[e3.x * HID + lane];
            float f4 = g_tmp[e4.x * HID + lane];
            float f5 = g_tmp[e5.x * HID + lane];
            float f6 = g_tmp[e6.x * HID + lane];
            float f7 = g_tmp[e7.x * HID + lane];
            acc += __int_as_float(e0.y) * f0;
            acc += __int_as_float(e1.y) * f1;
            acc += __int_as_float(e2.y) * f2;
            acc += __int_as_float(e3.y) * f3;
            acc += __int_as_float(e4.y) * f4;
            acc += __int_as_float(e5.y) * f5;
            acc += __int_as_float(e6.y) * f6;
            acc += __int_as_float(e7.y) * f7;
        }
        if (i + 4 <= end) {
            int2 e0 = g_edge[i + 0];
            int2 e1 = g_edge[i + 1];
            int2 e2 = g_edge[i + 2];
            int2 e3 = g_edge[i + 3];
            float f0 = g_tmp[e0.x * HID + lane];
            float f1 = g_tmp[e1.x * HID + lane];
            float f2 = g_tmp[e2.x * HID + lane];
            float f3 = g_tmp[e3.x * HID + lane];
            acc += __int_as_float(e0.y) * f0;
            acc += __int_as_float(e1.y) * f1;
            acc += __int_as_float(e2.y) * f2;
            acc += __int_as_float(e3.y) * f3;
            i += 4;
        }
        for (; i < end; i++) {
            int2 e0 = g_edge[i];
            acc += __int_as_float(e0.y) * g_tmp[e0.x * HID + lane];
        }
        if (out) out[v * HID + lane] = fmaxf(acc, 0.f);
        else     g_acc[v * HID + lane] = acc;
    }
    if (layer < 3) {   // BN stats via replicated atomics
        __shared__ float sh[16][64];
        float a = (v < n) ? acc : 0.f;
        sh[warp][lane]      = a;
        sh[warp][32 + lane] = a * a;
        __syncthreads();
        if (threadIdx.x < 64) {
            float t = 0.f;
#pragma unroll
            for (int w = 0; w < 16; w++) t += sh[w][threadIdx.x];
            int rep = blockIdx.x & (NREP - 1);
            atomicAdd(&g_statsR[(layer * NREP + rep) * 64 + threadIdx.x], t);
        }
    }
}

// ---------------- launch ----------------
extern "C" void kernel_launch(void* const* d_in, const int* in_sizes, int n_in,
                              void* d_out, int out_size) {
    const float* x  = (const float*)d_in[0];
    const int*   ei = (const int*)d_in[1];     // int32 (harness dtype)
    const float* w  = (const float*)d_in[2];
    const float* W0 = (const float*)d_in[3];
    const float* b0 = (const float*)d_in[4];
    const float* W1 = (const float*)d_in[5];
    const float* b1 = (const float*)d_in[6];
    const float* W2 = (const float*)d_in[7];
    const float* b2 = (const float*)d_in[8];
    const float* W3 = (const float*)d_in[9];
    const float* b3 = (const float*)d_in[10];
    const float* g0 = (const float*)d_in[11];
    const float* be0 = (const float*)d_in[12];
    const float* g1 = (const float*)d_in[13];
    const float* be1 = (const float*)d_in[14];
    const float* g2 = (const float*)d_in[15];
    const float* be2 = (const float*)d_in[16];
    float* out = (float*)d_out;

    const int n = in_sizes[0] / DIN;        // 100000
    const int e = in_sizes[2];              // 3200000
    const float invN = 1.0f / (float)n;

    const int TB = 256;
    const int gN   = (n + TB - 1) / TB;
    const int gE   = (e + TB - 1) / TB;
    const int gAgg = (n * 32 + AGG_T - 1) / AGG_T;  // 6250
    const int gRow = (n + 7) / 8;
    const int nb   = (n + SCAN_B - 1) / SCAN_B;     // 391

    // ---- CSR + normalization precompute ----
    k_init<<<gN, TB>>>(n);
    k_hist<<<gE, TB>>>(ei, w, e, n);
    k_scan_a<<<nb, SCAN_B>>>(n);
    k_scan_c<<<nb, SCAN_B>>>(n, e);
    k_csr_scatter<<<gE, TB>>>(ei, w, e, n);

    const float* Ws[4]  = {W0, W1, W2, W3};
    const float* bs[4]  = {b0, b1, b2, b3};
    const float* gs[3]  = {g0, g1, g2};
    const float* bes[3] = {be0, be1, be2};

    for (int layer = 0; layer < 4; layer++) {
        if (layer == 0)
            k_gemm128<<<gRow, TB>>>(x, Ws[0], n);
        else
            k_gemm32_bn<<<gRow, TB>>>(Ws[layer], gs[layer - 1],
                                      bes[layer - 1], n, invN, layer - 1);
        k_aggregate<<<gAgg, AGG_T>>>(bs[layer], n, layer,
                                     (layer == 3) ? out : nullptr);
    }
}

// round 13
// speedup vs baseline: 1.4393x; 1.0106x over previous
#include <cuda_runtime.h>
#include <cuda_fp16.h>
#include <cstdint>

#define NN 100000
#define EE 3200000
#define HID 32
#define DIN 128
#define SCAN_B 256
#define AGG_T 512
#define NREP 32                                 // stat replicas per layer

// ---------------- scratch ----------------
__device__ float g_tmp[NN * HID];   // dinv_r * (h @ W)  (gather source)
__device__ float g_acc[NN * HID];   // conv result
__device__ unsigned long long g_hist[NN];  // packed {count:12 | weight_fx:52}
__device__ float g_deg[NN];         // dinv
__device__ int   g_cnt[NN];         // counts, then CSR cursor
__device__ int   g_off[NN + 1];     // CSR offsets
__device__ int2  g_edge[EE];        // CSR: {src, float-bits of raw weight}
__device__ int   g_bsum[512];       // scan block sums
__device__ float g_statsR[3 * NREP * 64];  // replicated BN partials

// ---------------- prep ----------------
__global__ void k_init(int n) {
    int i = blockIdx.x * blockDim.x + threadIdx.x;
    if (i < n) g_hist[i] = 0ULL;
    if (i < 3 * NREP * 64) g_statsR[i] = 0.f;
}

// one packed atomic per edge: count += 1 (bit 52), weight += w * 2^32
__global__ void k_hist(const int* __restrict__ ei,
                       const float* __restrict__ w, int e_cnt, int n) {
    int e = blockIdx.x * blockDim.x + threadIdx.x;
    if (e < e_cnt) {
        int c = ei[e_cnt + e];
        c = min(max(c, 0), n - 1);
        unsigned long long wf =
            (unsigned long long)(fmaxf(w[e], 0.f) * 4294967296.0f + 0.5f);
        atomicAdd(&g_hist[c], (1ULL << 52) | wf);
    }
}

// scan_a fused with unpack + dinv
__global__ void k_scan_a(int n) {
    __shared__ int sh[SCAN_B];
    int i = blockIdx.x * SCAN_B + threadIdx.x;
    int cnt = 0;
    if (i < n) {
        unsigned long long h = g_hist[i];
        cnt = (int)(h >> 52);
        float wsum = (float)(h & ((1ULL << 52) - 1ULL)) * 2.3283064365386963e-10f
                     + 1.0f;   // + self-loop
        g_deg[i] = rsqrtf(wsum);
        g_cnt[i] = cnt;
    }
    sh[threadIdx.x] = cnt;
    __syncthreads();
    for (int off = SCAN_B / 2; off > 0; off >>= 1) {
        if (threadIdx.x < off) sh[threadIdx.x] += sh[threadIdx.x + off];
        __syncthreads();
    }
    if (threadIdx.x == 0) g_bsum[blockIdx.x] = sh[0];
}

// scan_c computes its own global offset from g_bsum
__global__ void k_scan_c(int n, int e_cnt) {
    __shared__ int sh[SCAN_B];
    __shared__ int base_s;
    int tid = threadIdx.x;
    int s = 0;
    for (int j = tid; j < blockIdx.x; j += SCAN_B) s += g_bsum[j];
    sh[tid] = s;
    __syncthreads();
    for (int off = SCAN_B / 2; off > 0; off >>= 1) {
        if (tid < off) sh[tid] += sh[tid + off];
        __syncthreads();
    }
    if (tid == 0) base_s = sh[0];
    __syncthreads();
    int base = base_s;
    __syncthreads();

    int i = blockIdx.x * SCAN_B + tid;
    int c = (i < n) ? g_cnt[i] : 0;
    sh[tid] = c;
    __syncthreads();
    for (int off = 1; off < SCAN_B; off <<= 1) {
        int v = (tid >= off) ? sh[tid - off] : 0;
        __syncthreads();
        sh[tid] += v;
        __syncthreads();
    }
    if (i < n) {
        int off = base + sh[tid] - c;
        g_off[i] = off;
        g_cnt[i] = off;
    }
    if (blockIdx.x == 0 && tid == 0) g_off[n] = e_cnt;
}

// stores raw {src, w} — NO random g_deg reads (norm factored into tmp/epilogue)
__global__ void k_csr_scatter(const int* __restrict__ ei,
                              const float* __restrict__ w, int e_cnt, int n) {
    int e = blockIdx.x * blockDim.x + threadIdx.x;
    if (e < e_cnt) {
        int r = ei[e];
        int c = ei[e_cnt + e];
        r = min(max(r, 0), n - 1);
        c = min(max(c, 0), n - 1);
        int pos = atomicAdd(&g_cnt[c], 1);
        g_edge[pos] = make_int2(r, __float_as_int(w[e]));
    }
}

// ---------------- transforms (scaled by dinv at write) ----------------
__global__ void k_gemm128(const float* __restrict__ x,
                          const float* __restrict__ W, int n) {
    __shared__ float Ws[DIN * HID];
    __shared__ float xs[8][DIN];
    int tid = threadIdx.x;
    for (int i = tid; i < DIN * HID; i += 256) Ws[i] = W[i];
    __syncthreads();
    int warp = tid >> 5, lane = tid & 31;
    int r = blockIdx.x * 8 + warp;
    if (r >= n) return;
#pragma unroll
    for (int j = 0; j < 4; j++)
        xs[warp][j * 32 + lane] = x[r * DIN + j * 32 + lane];
    __syncwarp();
    float sum = 0.f;
#pragma unroll
    for (int k = 0; k < DIN; k++) sum += xs[warp][k] * Ws[k * HID + lane];
    g_tmp[r * HID + lane] = sum * g_deg[r];
}

// prologue reduces the NREP stat replicas of the previous layer
__global__ void k_gemm32_bn(const float* __restrict__ W,
                            const float* __restrict__ g,
                            const float* __restrict__ be,
                            int n, float invN, int layerm1) {
    __shared__ float Ws[HID * HID];
    __shared__ float bn_s[HID], bn_b[HID];
    int tid = threadIdx.x;
    for (int i = tid; i < HID * HID; i += 256) Ws[i] = W[i];
    if (tid < 64) {
        const float* base = &g_statsR[layerm1 * NREP * 64];
        float s = 0.f;
#pragma unroll
        for (int r2 = 0; r2 < NREP; r2++) s += base[r2 * 64 + tid];
        if (tid < 32) bn_s[tid] = s;        // stash sum
        else          bn_b[tid - 32] = s;   // stash sumsq
    }
    __syncthreads();
    if (tid < HID) {
        float mu  = bn_s[tid] * invN;
        float var = bn_b[tid] * invN - mu * mu;
        float sc  = rsqrtf(var + 1e-5f) * g[tid];
        bn_s[tid] = sc;
        bn_b[tid] = be[tid] - mu * sc;
    }
    __syncthreads();
    int warp = tid >> 5, lane = tid & 31;
    int r = blockIdx.x * 8 + warp;
    if (r >= n) return;
    float mine = fmaxf(g_acc[r * HID + lane] * bn_s[lane] + bn_b[lane], 0.f);
    float sum = 0.f;
#pragma unroll
    for (int k = 0; k < HID; k++) {
        float xv = __shfl_sync(0xffffffffu, mine, k);
        sum += xv * Ws[k * HID + lane];
    }
    g_tmp[r * HID + lane] = sum * g_deg[r];
}

// ---------------- CSR gather-aggregate ----------------
// acc = b + dinv_v * ( t'[v] + sum_e w_e * t'[src_e] )
__global__ void __launch_bounds__(AGG_T)
k_aggregate(const float* __restrict__ b, int n, int layer,
            float* __restrict__ out) {
    int gid = blockIdx.x * AGG_T + threadIdx.x;
    int v = gid >> 5;
    int lane = gid & 31;
    int warp = threadIdx.x >> 5;
    float acc = 0.f;
    if (v < n) {
        int beg = g_off[v];
        int end = g_off[v + 1];
        float inner = g_tmp[v * HID + lane];   // self-loop (w=1)
        int i = beg;
        for (; i + 8 <= end; i += 8) {
            int2 e0 = g_edge[i + 0];
            int2 e1 = g_edge[i + 1];
            int2 e2 = g_edge[i + 2];
            int2 e3 = g_edge[i + 3];
            int2 e4 = g_edge[i + 4];
            int2 e5 = g_edge[i + 5];
            int2 e6 = g_edge[i + 6];
            int2 e7 = g_edge[i + 7];
            float f0 = g_tmp[e0.x * HID + lane];
            float f1 = g_tmp[e1.x * HID + lane];
            float f2 = g_tmp[e2.x * HID + lane];
            float f3 = g_tmp[e3.x * HID + lane];
            float f4 = g_tmp[e4.x * HID + lane];
            float f5 = g_tmp[e5.x * HID + lane];
            float f6 = g_tmp[e6.x * HID + lane];
            float f7 = g_tmp[e7.x * HID + lane];
            inner += __int_as_float(e0.y) * f0;
            inner += __int_as_float(e1.y) * f1;
            inner += __int_as_float(e2.y) * f2;
            inner += __int_as_float(e3.y) * f3;
            inner += __int_as_float(e4.y) * f4;
            inner += __int_as_float(e5.y) * f5;
            inner += __int_as_float(e6.y) * f6;
            inner += __int_as_float(e7.y) * f7;
        }
        if (i + 4 <= end) {
            int2 e0 = g_edge[i + 0];
            int2 e1 = g_edge[i + 1];
            int2 e2 = g_edge[i + 2];
            int2 e3 = g_edge[i + 3];
            float f0 = g_tmp[e0.x * HID + lane];
            float f1 = g_tmp[e1.x * HID + lane];
            float f2 = g_tmp[e2.x * HID + lane];
            float f3 = g_tmp[e3.x * HID + lane];
            inner += __int_as_float(e0.y) * f0;
            inner += __int_as_float(e1.y) * f1;
            inner += __int_as_float(e2.y) * f2;
            inner += __int_as_float(e3.y) * f3;
            i += 4;
        }
        for (; i < end; i++) {
            int2 e0 = g_edge[i];
            inner += __int_as_float(e0.y) * g_tmp[e0.x * HID + lane];
        }
        acc = b[lane] + g_deg[v] * inner;
        if (out) out[v * HID + lane] = fmaxf(acc, 0.f);
        else     g_acc[v * HID + lane] = acc;
    }
    if (layer < 3) {   // BN stats via replicated atomics
        __shared__ float sh[16][64];
        float a = (v < n) ? acc : 0.f;
        sh[warp][lane]      = a;
        sh[warp][32 + lane] = a * a;
        __syncthreads();
        if (threadIdx.x < 64) {
            float t = 0.f;
#pragma unroll
            for (int w = 0; w < 16; w++) t += sh[w][threadIdx.x];
            int rep = blockIdx.x & (NREP - 1);
            atomicAdd(&g_statsR[(layer * NREP + rep) * 64 + threadIdx.x], t);
        }
    }
}

// ---------------- launch ----------------
extern "C" void kernel_launch(void* const* d_in, const int* in_sizes, int n_in,
                              void* d_out, int out_size) {
    const float* x  = (const float*)d_in[0];
    const int*   ei = (const int*)d_in[1];     // int32 (harness dtype)
    const float* w  = (const float*)d_in[2];
    const float* W0 = (const float*)d_in[3];
    const float* b0 = (const float*)d_in[4];
    const float* W1 = (const float*)d_in[5];
    const float* b1 = (const float*)d_in[6];
    const float* W2 = (const float*)d_in[7];
    const float* b2 = (const float*)d_in[8];
    const float* W3 = (const float*)d_in[9];
    const float* b3 = (const float*)d_in[10];
    const float* g0 = (const float*)d_in[11];
    const float* be0 = (const float*)d_in[12];
    const float* g1 = (const float*)d_in[13];
    const float* be1 = (const float*)d_in[14];
    const float* g2 = (const float*)d_in[15];
    const float* be2 = (const float*)d_in[16];
    float* out = (float*)d_out;

    const int n = in_sizes[0] / DIN;        // 100000
    const int e = in_sizes[2];              // 3200000
    const float invN = 1.0f / (float)n;

    const int TB = 256;
    const int gN   = (n + TB - 1) / TB;
    const int gE   = (e + TB - 1) / TB;
    const int gAgg = (n * 32 + AGG_T - 1) / AGG_T;  // 6250
    const int gRow = (n + 7) / 8;
    const int nb   = (n + SCAN_B - 1) / SCAN_B;     // 391

    // ---- CSR + normalization precompute ----
    k_init<<<gN, TB>>>(n);
    k_hist<<<gE, TB>>>(ei, w, e, n);
    k_scan_a<<<nb, SCAN_B>>>(n);
    k_scan_c<<<nb, SCAN_B>>>(n, e);
    k_csr_scatter<<<gE, TB>>>(ei, w, e, n);

    const float* Ws[4]  = {W0, W1, W2, W3};
    const float* bs[4]  = {b0, b1, b2, b3};
    const float* gs[3]  = {g0, g1, g2};
    const float* bes[3] = {be0, be1, be2};

    for (int layer = 0; layer < 4; layer++) {
        if (layer == 0)
            k_gemm128<<<gRow, TB>>>(x, Ws[0], n);
        else
            k_gemm32_bn<<<gRow, TB>>>(Ws[layer], gs[layer - 1],
                                      bes[layer - 1], n, invN, layer - 1);
        k_aggregate<<<gAgg, AGG_T>>>(bs[layer], n, layer,
                                     (layer == 3) ? out : nullptr);
    }
}